// round 9
// baseline (speedup 1.0000x reference)
#include <cuda_runtime.h>
#include <stdint.h>

// GLCMAttention round 9: group-of-4 pixel RMW with exact register-side
// collision resolution (all loads before all stores -> 2 latency chains/row
// instead of 8). Rest identical to round-8 champion.
//  k1: GLCM hist (u8 per-thread regions, 64KB smem, 3 CTAs/SM) + feats + MLP
//      -> g_scale[bc]. Warp w owns rows [w*32,w*32+32), lane owns 8 cols.
//  k2: out = x * g_scale[bc], grid 2048, pure streaming (~72% DRAM).
//
// hist layout (bank == owner-lane for every access):
//   byte addr = warp<<13 | (q*8+qs)<<7 | lane<<2 | angle

#define HIST_BYTES 65536
#define SMEM_TOTAL (HIST_BYTES + 256*4 + 16*4 + 16)

__device__ float g_scale[512];

__device__ __forceinline__ unsigned q7(float v) { return (unsigned)(int)(v * 7.0f); }

// Thread t sums counter-id t across all 256 per-thread regions.
__device__ __forceinline__ unsigned flush_hist(const unsigned char* hist,
                                               int t, int lane)
{
    unsigned acc = 0;
    const unsigned sel = 1u << ((t & 3) * 8);          // extract byte 'angle'
    const unsigned pairbase = (unsigned)(t >> 2) << 7; // pair row (128B)
    const unsigned kst = (unsigned)(lane >> 2) & 7u;
    #pragma unroll
    for (int w = 0; w < 8; ++w) {
        unsigned base = ((unsigned)w << 13) | pairbase;
        #pragma unroll
        for (int k = 0; k < 8; ++k) {
            unsigned kk = ((unsigned)k + kst) & 7u;
            uint4 v = *(const uint4*)(hist + base + (kk << 4));
            acc = __dp4a(v.x, sel, acc);
            acc = __dp4a(v.y, sel, acc);
            acc = __dp4a(v.z, sel, acc);
            acc = __dp4a(v.w, sel, acc);
        }
    }
    return acc;
}

// Load strip-local row R (8 floats) into float array DF, zeros if OOB.
#define LOADA(DF, R)                                                         \
    {                                                                        \
        float4 aa = make_float4(0.f,0.f,0.f,0.f);                            \
        float4 bb = make_float4(0.f,0.f,0.f,0.f);                            \
        if (((R) <= 32) && ((grow + (R)) < 256)) {                           \
            const float4* p_ = (const float4*)(rowbase + (size_t)(R) * 256); \
            aa = p_[0]; bb = p_[1];                                          \
        }                                                                    \
        DF[0]=aa.x; DF[1]=aa.y; DF[2]=aa.z; DF[3]=aa.w;                      \
        DF[4]=bb.x; DF[5]=bb.y; DF[6]=bb.z; DF[7]=bb.w;                      \
    }

// Quantize float array SF -> unsigned array DQ + warp-edge shfls.
#define QUANTA(DQ, SF, LOUT, ROUT)                                           \
    {                                                                        \
        _Pragma("unroll")                                                    \
        for (int k_ = 0; k_ < 8; ++k_) DQ[k_] = q7(SF[k_]);                  \
        LOUT = __shfl_up_sync(0xFFFFFFFFu, DQ[7], 1);                        \
        if (lane == 0)  LOUT = 0u;                                           \
        ROUT = __shfl_down_sync(0xFFFFFFFFu, DQ[0], 1);                      \
        if (lane == 31) ROUT = 0u;                                           \
    }

// 4-pixel group RMW: all 16 loads first, exact collision-corrected
// increments (collisions only possible within the same angle byte),
// then 16 stores in program order (last writer carries full count).
#define GROUP4(J0)                                                           \
    {                                                                        \
        unsigned qp[4][4];                                                   \
        _Pragma("unroll")                                                    \
        for (int p_ = 0; p_ < 4; ++p_) {                                     \
            int j_ = (J0) + p_;                                              \
            unsigned q8_ = qc[j_] << 3;                                      \
            qp[p_][0] = q8_ + ((j_ == 0) ? Lc : qc[j_ - 1]);                 \
            qp[p_][1] = q8_ + ((j_ == 0) ? Ln : qn[j_ - 1]);                 \
            qp[p_][2] = q8_ + qn[j_];                                        \
            qp[p_][3] = q8_ + ((j_ == 7) ? Rn : qn[j_ + 1]);                 \
        }                                                                    \
        unsigned v[4][4];                                                    \
        _Pragma("unroll")                                                    \
        for (int p_ = 0; p_ < 4; ++p_) {                                     \
            _Pragma("unroll")                                                \
            for (int a_ = 0; a_ < 4; ++a_)                                   \
                v[p_][a_] = hb[(qp[p_][a_] << 7) + a_];                      \
        }                                                                    \
        _Pragma("unroll")                                                    \
        for (int a_ = 0; a_ < 4; ++a_) {                                     \
            unsigned i1_ = 1u + (unsigned)(qp[1][a_] == qp[0][a_]);          \
            unsigned i2_ = 1u + (unsigned)(qp[2][a_] == qp[0][a_])           \
                              + (unsigned)(qp[2][a_] == qp[1][a_]);          \
            unsigned i3_ = 1u + (unsigned)(qp[3][a_] == qp[0][a_])           \
                              + (unsigned)(qp[3][a_] == qp[1][a_])           \
                              + (unsigned)(qp[3][a_] == qp[2][a_]);          \
            hb[(qp[0][a_] << 7) + a_] = (unsigned char)(v[0][a_] + 1u);      \
            hb[(qp[1][a_] << 7) + a_] = (unsigned char)(v[1][a_] + i1_);     \
            hb[(qp[2][a_] << 7) + a_] = (unsigned char)(v[2][a_] + i2_);     \
            hb[(qp[3][a_] << 7) + a_] = (unsigned char)(v[3][a_] + i3_);     \
        }                                                                    \
    }

// Pipeline step: quantize row Y+2 (in FB), prefetch row Y+4 (into FB),
// RMW row Y (qc vs qn), rotate state.
#define STEPA(Y, FB)                                                         \
    {                                                                        \
        unsigned t8[8], Lt, Rt;                                              \
        QUANTA(t8, FB, Lt, Rt)                                               \
        LOADA(FB, (Y)+4)                                                     \
        GROUP4(0)                                                            \
        GROUP4(4)                                                            \
        _Pragma("unroll")                                                    \
        for (int k_ = 0; k_ < 8; ++k_) { qc[k_] = qn[k_]; qn[k_] = t8[k_]; } \
        Lc = Ln; Ln = Lt; Rn = Rt;                                           \
    }

__global__ void __launch_bounds__(256, 3)
glcm_hist_kernel(const float* __restrict__ x,
                 const float* __restrict__ W1,
                 const float* __restrict__ W2)
{
    extern __shared__ unsigned char smem[];
    unsigned char* hist   = smem;
    unsigned*      totals = (unsigned*)(smem + HIST_BYTES);
    float*         feats  = (float*)(totals + 256);

    const int t = threadIdx.x, lane = t & 31, w = t >> 5;
    const int bc = blockIdx.x;
    const float* xp = x + (size_t)bc * 65536;

    // ---- zero hist ----
    uint4* h4 = (uint4*)hist;
    #pragma unroll
    for (int i = 0; i < 16; ++i) h4[t + (i << 8)] = make_uint4(0u,0u,0u,0u);
    __syncthreads();

    unsigned char* hb = hist + (w << 13) + (lane << 2);

    const int grow = w << 5;                       // strip's global row 0
    const float* rowbase = xp + grow * 256 + (lane << 3);

    // ---- prologue: rows 0,1 quantized; rows 2,3 prefetched ----
    unsigned qc[8], qn[8], Lc, Ln, Rn;
    float fb0[8], fb1[8];
    {
        unsigned dum;
        LOADA(fb0, 0)
        QUANTA(qc, fb0, Lc, dum)
        (void)dum;
        LOADA(fb0, 1)
        QUANTA(qn, fb0, Ln, Rn)
    }
    LOADA(fb0, 2)
    LOADA(fb1, 3)

    unsigned acc = 0;

    // ---- phase 1: rows 0..15 (max 8*16=128 per u8 counter) ----
    #pragma unroll 2
    for (int y = 0; y < 16; y += 2) {
        STEPA(y,   fb0)
        STEPA(y+1, fb1)
    }
    __syncthreads();
    acc += flush_hist(hist, t, lane);
    __syncthreads();
    #pragma unroll
    for (int i = 0; i < 16; ++i) h4[t + (i << 8)] = make_uint4(0u,0u,0u,0u);
    __syncthreads();

    // ---- phase 2: rows 16..31 ----
    #pragma unroll 2
    for (int y = 16; y < 32; y += 2) {
        STEPA(y,   fb0)
        STEPA(y+1, fb1)
    }
    __syncthreads();
    acc += flush_hist(hist, t, lane);
    totals[t] = acc;
    __syncthreads();

    // ---- features: warp 0, lane l -> angle = l>>3, row i = l&7 ----
    if (t < 32) {
        int angle = t >> 3;
        int sub   = t & 7;
        const float inv = 1.0f / 65536.0f;
        float fi = (float)sub;
        float contrast = 0.f, homog = 0.f, energy = 0.f, corr = 0.f;
        #pragma unroll
        for (int j = 0; j < 8; ++j) {
            float p = (float)totals[(((sub << 3) + j) << 2) + angle] * inv;
            float d = fi - (float)j;
            contrast += d * d * p;
            homog    += p / (1.0f + fabsf(d));
            energy   += p * p;
            corr     += (fi - 3.5f) * ((float)j - 3.5f) * p;
        }
        #pragma unroll
        for (int off = 4; off; off >>= 1) {
            contrast += __shfl_down_sync(0xFFFFFFFFu, contrast, off);
            homog    += __shfl_down_sync(0xFFFFFFFFu, homog,    off);
            energy   += __shfl_down_sync(0xFFFFFFFFu, energy,   off);
            corr     += __shfl_down_sync(0xFFFFFFFFu, corr,     off);
        }
        if (sub == 0) {
            feats[angle * 4 + 0] = contrast;
            feats[angle * 4 + 1] = homog;
            feats[angle * 4 + 2] = energy;
            feats[angle * 4 + 3] = corr * (1.0f / 6.000001f);  // /(std^2+1e-6)
        }
    }
    __syncthreads();

    // ---- MLP diagonal -> g_scale[bc] ----
    if (t < 16) {
        float h = 0.f;
        #pragma unroll
        for (int f = 0; f < 16; ++f) h += feats[f] * W1[f * 16 + t];
        h = fmaxf(h, 0.0f);
        int c = bc & 63;
        float v = h * W2[t * 64 + c];
        #pragma unroll
        for (int off = 8; off; off >>= 1)
            v += __shfl_down_sync(0x0000FFFFu, v, off);
        if (t == 0)
            g_scale[bc] = 1.0f + 1.0f / (1.0f + expf(-v));
    }
}

// k2: pure streaming scale. 4 blocks/image, 2048 blocks.
__global__ void __launch_bounds__(256)
glcm_scale_kernel(const float* __restrict__ x, float* __restrict__ out)
{
    const int blk = blockIdx.x;
    const float s = g_scale[blk >> 2];
    const float4* xs = (const float4*)x + (size_t)blk * 4096;
    float4*       os = (float4*)out     + (size_t)blk * 4096;
    const int t = threadIdx.x;
    #pragma unroll
    for (int k = 0; k < 16; ++k) {
        int i = t + (k << 8);
        float4 v = xs[i];
        v.x *= s; v.y *= s; v.z *= s; v.w *= s;
        os[i] = v;
    }
}

extern "C" void kernel_launch(void* const* d_in, const int* in_sizes, int n_in,
                              void* d_out, int out_size)
{
    (void)in_sizes; (void)n_in; (void)out_size;
    const float* x  = (const float*)d_in[0];
    const float* W1 = (const float*)d_in[1];
    const float* W2 = (const float*)d_in[2];
    float* out = (float*)d_out;

    cudaFuncSetAttribute(glcm_hist_kernel,
                         cudaFuncAttributeMaxDynamicSharedMemorySize, SMEM_TOTAL);
    glcm_hist_kernel<<<512, 256, SMEM_TOTAL>>>(x, W1, W2);
    glcm_scale_kernel<<<2048, 256>>>(x, out);
}